// round 6
// baseline (speedup 1.0000x reference)
#include <cuda_runtime.h>
#include <cstdint>

#define B_ 2
#define S_ 2048
#define D_ 1024
#define H_ 16
#define DK_ 64
#define DV_ 64
#define SEG_ 512
#define SL_ 128
#define L_ 768
#define NSEG_ 4

// ---------------- scratch (device globals: allocation-free) ----------------
__device__ float g_kqvf[(size_t)B_*H_*S_*192];   // full-seq K|Q|V interleaved
__device__ float g_stp [(size_t)B_*H_*SL_*192];  // state K|Q|V projection
__device__ float g_att1[(size_t)B_*H_*L_*64];
__device__ float g_kqv2[(size_t)B_*H_*L_*384];   // k2|q2|v2 interleaved
__device__ float g_a2  [(size_t)B_*640*2048];    // unified gathered a2r(512) | a2er(128)
__device__ float g_stA[(size_t)B_*SL_*D_];
__device__ float g_stB[(size_t)B_*SL_*D_];
__device__ float g_part[(size_t)4*1024*1024];
__device__ float g_WkqvF[(size_t)H_*D_*192];
__device__ float g_WstP [(size_t)H_*D_*192];
__device__ float g_W2ss [(size_t)H_*64*384];
__device__ float g_W2mid[(size_t)H_*64*384];
__device__ float g_W2se [(size_t)H_*64*384];

struct BTab { const float* p[8]; };

// ---------------- tf32 helpers ----------------
__device__ __forceinline__ uint32_t f2tf(float f) {
    uint32_t u;
    asm("cvt.rna.tf32.f32 %0, %1;" : "=r"(u) : "f"(f));
    return u;
}
__device__ __forceinline__ void mma8(float* c, const uint32_t* a, const uint32_t* b) {
    asm volatile(
        "mma.sync.aligned.m16n8k8.row.col.f32.tf32.tf32.f32 "
        "{%0,%1,%2,%3}, {%4,%5,%6,%7}, {%8,%9}, {%0,%1,%2,%3};\n"
        : "+f"(c[0]), "+f"(c[1]), "+f"(c[2]), "+f"(c[3])
        : "r"(a[0]), "r"(a[1]), "r"(a[2]), "r"(a[3]), "r"(b[0]), "r"(b[1]));
}
__device__ __forceinline__ int kperm(int k) {
    int j = k & 7;
    return (k & ~7) + ((j < 4) ? (j << 1) : ((j << 1) - 7));
}

// ---------------- batched strided tf32 tensor-core GEMM ----------------
// useTab: B matrix selected per M-row-block from tab.p[blockIdx.y]
template<int BM, int BN, int WM, int WN, bool TB>
__global__ void __launch_bounds__(256) gemm_t(
    const float* __restrict__ A, const float* __restrict__ Bm0, float* __restrict__ C,
    int M, int N, int K, int lda, int ldb, int ldc,
    long long aSB, long long aSH, long long bSB, long long bSH,
    long long cSB, long long cSH, int Hd, int Zr,
    int sk, int Kc, long long pcs, int useTab, BTab tab)
{
    constexpr int BK = 16;
    constexpr int KS = BK / 8;
    constexpr int MF = WM / 16;
    constexpr int NF = WN / 8;
    constexpr int WCOL = BN / WN;
    constexpr int NA4 = BM * BK / 1024;
    constexpr int NB4 = BN * BK / 1024;
    constexpr int KQ = BK / 4;

    int z = blockIdx.z;
    int ks = 0, zz = z;
    if (sk > 1) { ks = z / Zr; zz = z - ks * Zr; }
    int b = zz / Hd, h = zz - b * Hd;
    const float* Bm = useTab ? tab.p[blockIdx.y] : Bm0;
    A  += (long long)b * aSB + (long long)h * aSH;
    Bm += (long long)b * bSB + (long long)h * bSH;
    C  += (long long)ks * pcs + (long long)b * cSB + (long long)h * cSH;

    int row0 = blockIdx.y * BM;
    int col0 = blockIdx.x * BN;

    int kBeg = ks * Kc;
    int nk = Kc / BK;

    __shared__ uint32_t As[2][BM][BK + 4];
    __shared__ uint32_t Bs[2][BN][BK + 4];

    int tid = threadIdx.x;
    int w   = tid >> 5;
    int lane = tid & 31;
    int g = lane >> 2, q = lane & 3;
    int warpM = w / WCOL, warpN = w % WCOL;
    int wr = warpM * WM;
    int wc = warpN * WN;

    float4 ag[NA4], bg[NB4];

    {
        int kb = kBeg;
        #pragma unroll
        for (int i = 0; i < NA4; i++) {
            int f = tid + i * 256; int r = f / KQ; int c4 = (f % KQ) << 2;
            float4 v = *(const float4*)(A + (long long)(row0 + r) * lda + kb + c4);
            As[0][r][kperm(c4+0)] = f2tf(v.x);
            As[0][r][kperm(c4+1)] = f2tf(v.y);
            As[0][r][kperm(c4+2)] = f2tf(v.z);
            As[0][r][kperm(c4+3)] = f2tf(v.w);
        }
        if (!TB) {
            #pragma unroll
            for (int i = 0; i < NB4; i++) {
                int f = tid + i * 256; int kr = f / (BN/4); int n4 = (f % (BN/4)) << 2;
                float4 v = *(const float4*)(Bm + (long long)(kb + kr) * ldb + col0 + n4);
                int kp = kperm(kr);
                Bs[0][n4+0][kp] = f2tf(v.x);
                Bs[0][n4+1][kp] = f2tf(v.y);
                Bs[0][n4+2][kp] = f2tf(v.z);
                Bs[0][n4+3][kp] = f2tf(v.w);
            }
        } else {
            #pragma unroll
            for (int i = 0; i < NB4; i++) {
                int f = tid + i * 256; int r = f / KQ; int c4 = (f % KQ) << 2;
                float4 v = *(const float4*)(Bm + (long long)(col0 + r) * ldb + kb + c4);
                Bs[0][r][kperm(c4+0)] = f2tf(v.x);
                Bs[0][r][kperm(c4+1)] = f2tf(v.y);
                Bs[0][r][kperm(c4+2)] = f2tf(v.z);
                Bs[0][r][kperm(c4+3)] = f2tf(v.w);
            }
        }
    }
    __syncthreads();

    float acc[MF][NF][4];
    #pragma unroll
    for (int i = 0; i < MF; i++)
        #pragma unroll
        for (int j = 0; j < NF; j++)
            #pragma unroll
            for (int e = 0; e < 4; e++) acc[i][j][e] = 0.f;

    int cur = 0;
    for (int t = 0; t < nk; t++) {
        if (t + 1 < nk) {
            int kb = kBeg + (t + 1) * BK;
            #pragma unroll
            for (int i = 0; i < NA4; i++) {
                int f = tid + i * 256; int r = f / KQ; int c4 = (f % KQ) << 2;
                ag[i] = *(const float4*)(A + (long long)(row0 + r) * lda + kb + c4);
            }
            if (!TB) {
                #pragma unroll
                for (int i = 0; i < NB4; i++) {
                    int f = tid + i * 256; int kr = f / (BN/4); int n4 = (f % (BN/4)) << 2;
                    bg[i] = *(const float4*)(Bm + (long long)(kb + kr) * ldb + col0 + n4);
                }
            } else {
                #pragma unroll
                for (int i = 0; i < NB4; i++) {
                    int f = tid + i * 256; int r = f / KQ; int c4 = (f % KQ) << 2;
                    bg[i] = *(const float4*)(Bm + (long long)(col0 + r) * ldb + kb + c4);
                }
            }
        }
        #pragma unroll
        for (int s = 0; s < KS; s++) {
            uint32_t af[MF][4], bf[NF][2];
            #pragma unroll
            for (int i = 0; i < MF; i++) {
                uint2 lo = *(const uint2*)&As[cur][wr + 16*i + g    ][8*s + 2*q];
                uint2 hi = *(const uint2*)&As[cur][wr + 16*i + g + 8][8*s + 2*q];
                af[i][0] = lo.x; af[i][1] = hi.x; af[i][2] = lo.y; af[i][3] = hi.y;
            }
            #pragma unroll
            for (int j = 0; j < NF; j++) {
                uint2 bb = *(const uint2*)&Bs[cur][wc + 8*j + g][8*s + 2*q];
                bf[j][0] = bb.x; bf[j][1] = bb.y;
            }
            #pragma unroll
            for (int i = 0; i < MF; i++)
                #pragma unroll
                for (int j = 0; j < NF; j++)
                    mma8(acc[i][j], af[i], bf[j]);
        }
        if (t + 1 < nk) {
            int nxt = cur ^ 1;
            #pragma unroll
            for (int i = 0; i < NA4; i++) {
                int f = tid + i * 256; int r = f / KQ; int c4 = (f % KQ) << 2;
                As[nxt][r][kperm(c4+0)] = f2tf(ag[i].x);
                As[nxt][r][kperm(c4+1)] = f2tf(ag[i].y);
                As[nxt][r][kperm(c4+2)] = f2tf(ag[i].z);
                As[nxt][r][kperm(c4+3)] = f2tf(ag[i].w);
            }
            if (!TB) {
                #pragma unroll
                for (int i = 0; i < NB4; i++) {
                    int f = tid + i * 256; int kr = f / (BN/4); int n4 = (f % (BN/4)) << 2;
                    int kp = kperm(kr);
                    Bs[nxt][n4+0][kp] = f2tf(bg[i].x);
                    Bs[nxt][n4+1][kp] = f2tf(bg[i].y);
                    Bs[nxt][n4+2][kp] = f2tf(bg[i].z);
                    Bs[nxt][n4+3][kp] = f2tf(bg[i].w);
                }
            } else {
                #pragma unroll
                for (int i = 0; i < NB4; i++) {
                    int f = tid + i * 256; int r = f / KQ; int c4 = (f % KQ) << 2;
                    Bs[nxt][r][kperm(c4+0)] = f2tf(bg[i].x);
                    Bs[nxt][r][kperm(c4+1)] = f2tf(bg[i].y);
                    Bs[nxt][r][kperm(c4+2)] = f2tf(bg[i].z);
                    Bs[nxt][r][kperm(c4+3)] = f2tf(bg[i].w);
                }
            }
            __syncthreads();
            cur = nxt;
        }
    }

    #pragma unroll
    for (int i = 0; i < MF; i++) {
        #pragma unroll
        for (int j = 0; j < NF; j++) {
            int r0 = row0 + wr + 16*i + g;
            int c0 = col0 + wc + 8*j + 2*q;
            *(float2*)(C + (long long)r0 * ldc + c0) = make_float2(acc[i][j][0], acc[i][j][1]);
            *(float2*)(C + (long long)(r0 + 8) * ldc + c0) = make_float2(acc[i][j][2], acc[i][j][3]);
        }
    }
}

// ---------------- fused flash attention (tf32 mma, online softmax) ----------
// GATHER=0 (attn1): region-mapped inputs [state; segment; state]; dense out0.
// GATHER=1 (attn2): dense input b1; skip rows [0,SL); write unified a2 layout.
template<int DH, bool GATHER>
__global__ void __launch_bounds__(256) flash_k(
    const float* __restrict__ b1, const float* __restrict__ b2, int ld,
    long long b1S, long long b2S, int qoff, int koff, int voff,
    float* __restrict__ out0)
{
    constexpr int BR = 128, BC = 64;
    constexpr int QW = DH + 4, KW = DH + 4, VW = BC + 4, SW = BC + 4;
    extern __shared__ uint32_t sm[];
    uint32_t* Qs = sm;
    uint32_t* Ks = Qs + BR * QW;
    uint32_t* Vs = Ks + BC * KW;
    uint32_t* Ss = Vs + DH * VW;

    int bh = blockIdx.y;
    int b = bh / H_, h = bh - b * H_;

    const float* stb  = b1 + (long long)bh * b1S;
    const float* segb = GATHER ? stb : (b2 + (long long)bh * b2S);

    int row0 = (GATHER ? (blockIdx.x + 1) : blockIdx.x) * BR;

    // Q tile base (rows relative to tile start)
    const float* Qb;
    if (GATHER) {
        Qb = stb + (long long)row0 * ld;
    } else {
        if (row0 < SL_)            Qb = stb;
        else if (row0 < SL_+SEG_)  Qb = segb + (long long)(row0 - SL_) * ld;
        else                       Qb = stb;
    }

    int tid = threadIdx.x, w = tid >> 5, lane = tid & 31;
    int g = lane >> 2, q = lane & 3;
    int wr = w * 16;

    constexpr int NQ4 = BR * DH / 1024;
    #pragma unroll
    for (int i = 0; i < NQ4; i++) {
        int f = tid + i * 256; int r = f / (DH/4); int c4 = (f % (DH/4)) << 2;
        float4 v = *(const float4*)(Qb + (long long)r * ld + qoff + c4);
        Qs[r*QW + kperm(c4+0)] = f2tf(v.x);
        Qs[r*QW + kperm(c4+1)] = f2tf(v.y);
        Qs[r*QW + kperm(c4+2)] = f2tf(v.z);
        Qs[r*QW + kperm(c4+3)] = f2tf(v.w);
    }

    float Ofr[DH/8][4];
    #pragma unroll
    for (int j = 0; j < DH/8; j++)
        #pragma unroll
        for (int e = 0; e < 4; e++) Ofr[j][e] = 0.f;
    float m_a = -1e30f, m_b = -1e30f, l_a = 0.f, l_b = 0.f;
    int row_a = row0 + wr + g, row_b = row_a + 8;

    int nb = row0 / BC + 2;
    constexpr int NK4 = BC * DH / 1024;

    for (int cb = 0; cb < nb; cb++) {
        int c0 = cb * BC;
        // K/V tile base (region-uniform: BC=64 divides SL and SEG)
        const float* Kb;
        if (GATHER) {
            Kb = stb + (long long)c0 * ld;
        } else {
            if (c0 < SL_)            Kb = stb + (long long)c0 * ld;
            else if (c0 < SL_+SEG_)  Kb = segb + (long long)(c0 - SL_) * ld;
            else                     Kb = stb + (long long)(c0 - SL_ - SEG_) * ld;
        }
        __syncthreads();
        #pragma unroll
        for (int i = 0; i < NK4; i++) {
            int f = tid + i * 256; int r = f / (DH/4); int c4 = (f % (DH/4)) << 2;
            float4 v = *(const float4*)(Kb + (long long)r * ld + koff + c4);
            Ks[r*KW + kperm(c4+0)] = f2tf(v.x);
            Ks[r*KW + kperm(c4+1)] = f2tf(v.y);
            Ks[r*KW + kperm(c4+2)] = f2tf(v.z);
            Ks[r*KW + kperm(c4+3)] = f2tf(v.w);
        }
        #pragma unroll
        for (int i = 0; i < NK4; i++) {
            int f = tid + i * 256; int c = f / (DH/4); int d4 = (f % (DH/4)) << 2;
            float4 v = *(const float4*)(Kb + (long long)c * ld + voff + d4);
            int kp = kperm(c);
            Vs[(d4+0)*VW + kp] = f2tf(v.x);
            Vs[(d4+1)*VW + kp] = f2tf(v.y);
            Vs[(d4+2)*VW + kp] = f2tf(v.z);
            Vs[(d4+3)*VW + kp] = f2tf(v.w);
        }
        __syncthreads();

        float sfr[BC/8][4];
        #pragma unroll
        for (int j = 0; j < BC/8; j++)
            #pragma unroll
            for (int e = 0; e < 4; e++) sfr[j][e] = 0.f;
        #pragma unroll
        for (int s = 0; s < DH/8; s++) {
            uint32_t af[4];
            uint2 lo = *(const uint2*)&Qs[(wr+g  )*QW + 8*s + 2*q];
            uint2 hi = *(const uint2*)&Qs[(wr+g+8)*QW + 8*s + 2*q];
            af[0] = lo.x; af[1] = hi.x; af[2] = lo.y; af[3] = hi.y;
            #pragma unroll
            for (int j = 0; j < BC/8; j++) {
                uint2 bb = *(const uint2*)&Ks[(8*j+g)*KW + 8*s + 2*q];
                uint32_t bf[2] = {bb.x, bb.y};
                mma8(sfr[j], af, bf);
            }
        }

        bool needm = (c0 + BC - 1 > row0 + wr);
        float mb_a = -1e30f, mb_b = -1e30f;
        #pragma unroll
        for (int j = 0; j < BC/8; j++) {
            int col = c0 + 8*j + 2*q;
            float s0 = sfr[j][0]*0.125f, s1 = sfr[j][1]*0.125f;
            float s2 = sfr[j][2]*0.125f, s3 = sfr[j][3]*0.125f;
            if (needm) {
                if (col     > row_a) s0 = -1e30f;
                if (col + 1 > row_a) s1 = -1e30f;
                if (col     > row_b) s2 = -1e30f;
                if (col + 1 > row_b) s3 = -1e30f;
            }
            sfr[j][0]=s0; sfr[j][1]=s1; sfr[j][2]=s2; sfr[j][3]=s3;
            mb_a = fmaxf(mb_a, fmaxf(s0, s1));
            mb_b = fmaxf(mb_b, fmaxf(s2, s3));
        }
        mb_a = fmaxf(mb_a, __shfl_xor_sync(0xffffffffu, mb_a, 1));
        mb_a = fmaxf(mb_a, __shfl_xor_sync(0xffffffffu, mb_a, 2));
        mb_b = fmaxf(mb_b, __shfl_xor_sync(0xffffffffu, mb_b, 1));
        mb_b = fmaxf(mb_b, __shfl_xor_sync(0xffffffffu, mb_b, 2));
        float mn_a = fmaxf(m_a, mb_a), mn_b = fmaxf(m_b, mb_b);
        float ra = __expf(m_a - mn_a), rb = __expf(m_b - mn_b);
        float sa = 0.f, sb = 0.f;
        #pragma unroll
        for (int j = 0; j < BC/8; j++) {
            float p0 = __expf(sfr[j][0] - mn_a), p1 = __expf(sfr[j][1] - mn_a);
            float p2 = __expf(sfr[j][2] - mn_b), p3 = __expf(sfr[j][3] - mn_b);
            sa += p0 + p1; sb += p2 + p3;
            int cc = 8*j + 2*q;
            Ss[(wr+g  )*SW + kperm(cc  )] = f2tf(p0);
            Ss[(wr+g  )*SW + kperm(cc+1)] = f2tf(p1);
            Ss[(wr+g+8)*SW + kperm(cc  )] = f2tf(p2);
            Ss[(wr+g+8)*SW + kperm(cc+1)] = f2tf(p3);
        }
        sa += __shfl_xor_sync(0xffffffffu, sa, 1);
        sa += __shfl_xor_sync(0xffffffffu, sa, 2);
        sb += __shfl_xor_sync(0xffffffffu, sb, 1);
        sb += __shfl_xor_sync(0xffffffffu, sb, 2);
        l_a = l_a * ra + sa; l_b = l_b * rb + sb;
        m_a = mn_a; m_b = mn_b;
        #pragma unroll
        for (int j2 = 0; j2 < DH/8; j2++) {
            Ofr[j2][0] *= ra; Ofr[j2][1] *= ra;
            Ofr[j2][2] *= rb; Ofr[j2][3] *= rb;
        }
        __syncwarp();

        #pragma unroll
        for (int s = 0; s < BC/8; s++) {
            uint32_t af[4];
            uint2 lo = *(const uint2*)&Ss[(wr+g  )*SW + 8*s + 2*q];
            uint2 hi = *(const uint2*)&Ss[(wr+g+8)*SW + 8*s + 2*q];
            af[0] = lo.x; af[1] = hi.x; af[2] = lo.y; af[3] = hi.y;
            #pragma unroll
            for (int j2 = 0; j2 < DH/8; j2++) {
                uint2 bb = *(const uint2*)&Vs[(8*j2+g)*VW + 8*s + 2*q];
                uint32_t bf[2] = {bb.x, bb.y};
                mma8(Ofr[j2], af, bf);
            }
        }
    }

    float ia = 1.f / l_a, ib = 1.f / l_b;
    if (!GATHER) {
        float* oa = out0 + (long long)bh * L_ * DH + (long long)row_a * DH;
        float* ob = out0 + (long long)bh * L_ * DH + (long long)row_b * DH;
        #pragma unroll
        for (int j2 = 0; j2 < DH/8; j2++) {
            int col = 8*j2 + 2*q;
            *(float2*)(oa + col) = make_float2(Ofr[j2][0]*ia, Ofr[j2][1]*ia);
            *(float2*)(ob + col) = make_float2(Ofr[j2][2]*ib, Ofr[j2][3]*ib);
        }
    } else {
        #pragma unroll
        for (int rr = 0; rr < 2; rr++) {
            int s_abs = (rr == 0) ? row_a : row_b;
            float inv = (rr == 0) ? ia : ib;
            long long row;
            if (s_abs < SL_ + SEG_) {
                int s = s_abs - SL_;
                row = (long long)b * 640 + (h << 5) + (s >> 4);
                s_abs = s;
            } else {
                int s = s_abs - (SL_ + SEG_);
                row = (long long)b * 640 + 512 + (h << 3) + (s >> 4);
                s_abs = s;
            }
            float* dst = out0 + row * 2048 + ((s_abs & 15) << 7);
            #pragma unroll
            for (int j2 = 0; j2 < DH/8; j2++) {
                int col = 8*j2 + 2*q;
                float v0 = Ofr[j2][rr ? 2 : 0] * inv;
                float v1 = Ofr[j2][rr ? 3 : 1] * inv;
                *(float2*)(dst + col) = make_float2(v0, v1);
            }
        }
    }
}

// generic split-K reduce
__global__ void reduceK(float* __restrict__ C, const float* __restrict__ part,
    int sk, long long chunk, int M, int N, int ldc,
    long long cSB, long long cSH, int Hd)
{
    long long idx = (long long)blockIdx.x * blockDim.x + threadIdx.x;
    if (idx >= chunk) return;
    int n = (int)(idx % N);
    long long t = idx / N;
    int m = (int)(t % M);
    int zz = (int)(t / M);
    int b = zz / Hd, h = zz - b * Hd;
    float s = 0.f;
    for (int i = 0; i < sk; i++) s += part[(long long)i * chunk + idx];
    C[(long long)b * cSB + (long long)h * cSH + (long long)m * ldc + n] = s;
}

// split-K reduce for merged out/state GEMM (rows 0-511 -> out, 512-639 -> stn)
__global__ void reduceOS(float* __restrict__ outseg, float* __restrict__ stn,
    const float* __restrict__ part, int sk, long long chunk)
{
    long long idx = (long long)blockIdx.x * blockDim.x + threadIdx.x;
    if (idx >= chunk) return;
    int n = (int)(idx % D_);
    long long t = idx / D_;
    int m = (int)(t % 640);
    int b = (int)(t / 640);
    float s = 0.f;
    for (int i = 0; i < sk; i++) s += part[(long long)i * chunk + idx];
    if (m < 512) outseg[(long long)b * (S_*D_) + (long long)m * D_ + n] = s;
    else         stn[(long long)b * (SL_*D_) + (long long)(m - 512) * D_ + n] = s;
}

__global__ void pack3(float* __restrict__ dst, const float* __restrict__ s0,
                      const float* __restrict__ s1, const float* __restrict__ s2,
                      int n, int w)
{
    int idx = blockIdx.x * blockDim.x + threadIdx.x;
    int tot = n * 3 * w;
    if (idx >= tot) return;
    int c = idx % w; int o = (idx / w) % 3; int i = idx / (3 * w);
    const float* s = (o == 0) ? s0 : ((o == 1) ? s1 : s2);
    dst[idx] = s[(size_t)i * w + c];
}

__global__ void bcast_state(float* __restrict__ st, const float* __restrict__ state)
{
    int idx = blockIdx.x * blockDim.x + threadIdx.x;
    const int total = B_ * SL_ * D_;
    if (idx >= total) return;
    st[idx] = state[idx % (SL_ * D_)];
}

__global__ void copy_f(float* __restrict__ dst, const float* __restrict__ src, int n)
{
    int idx = blockIdx.x * blockDim.x + threadIdx.x;
    if (idx < n) dst[idx] = src[idx];
}

// ---------------- host ----------------
static float* s_part = nullptr;

static void G(bool tb, const float* A, const float* Bm, float* C,
              int M, int N, int K, int lda, int ldb, int ldc,
              long long aSB, long long aSH, long long bSB, long long bSH,
              long long cSB, long long cSH, int Hd, int Z, int sk = 1,
              int useTab = 0, BTab tab = {}, int customReduce = 0)
{
    int Kc = K / sk;
    long long pcs = 0;
    float* Cout = C;
    long long csb = cSB, csh = cSH;
    int ldc2 = ldc;
    if (sk > 1) {
        pcs = (long long)Z * M * N;
        Cout = s_part; ldc2 = N;
        csh = (long long)M * N;
        csb = (long long)Hd * M * N;
    }
    dim3 blk(256);
    if (N % 128 == 0) {
        dim3 grid(N / 128, (M + 127) / 128, Z * sk);
        if (tb) gemm_t<128,128,64,32,true ><<<grid, blk>>>(A, Bm, Cout, M, N, K, lda, ldb, ldc2,
            aSB, aSH, bSB, bSH, csb, csh, Hd, Z, sk, Kc, pcs, useTab, tab);
        else    gemm_t<128,128,64,32,false><<<grid, blk>>>(A, Bm, Cout, M, N, K, lda, ldb, ldc2,
            aSB, aSH, bSB, bSH, csb, csh, Hd, Z, sk, Kc, pcs, useTab, tab);
    } else {
        dim3 grid(N / 64, (M + 127) / 128, Z * sk);
        if (tb) gemm_t<128,64,32,32,true ><<<grid, blk>>>(A, Bm, Cout, M, N, K, lda, ldb, ldc2,
            aSB, aSH, bSB, bSH, csb, csh, Hd, Z, sk, Kc, pcs, useTab, tab);
        else    gemm_t<128,64,32,32,false><<<grid, blk>>>(A, Bm, Cout, M, N, K, lda, ldb, ldc2,
            aSB, aSH, bSB, bSH, csb, csh, Hd, Z, sk, Kc, pcs, useTab, tab);
    }
    if (sk > 1 && !customReduce) {
        long long chunk = (long long)Z * M * N;
        reduceK<<<(unsigned)((chunk + 255) / 256), 256>>>(C, s_part, sk, chunk,
            M, N, ldc, cSB, cSH, Hd);
    }
}

extern "C" void kernel_launch(void* const* d_in, const int* in_sizes, int n_in,
                              void* d_out, int out_size)
{
    const float* x       = (const float*)d_in[0];
    const float* state   = (const float*)d_in[1];
    const float* Wk      = (const float*)d_in[2];
    const float* Wq      = (const float*)d_in[3];
    const float* Wv      = (const float*)d_in[4];
    const float* W2k     = (const float*)d_in[5];
    const float* Wout    = (const float*)d_in[6];
    const float* Wk_st   = (const float*)d_in[7];
    const float* Wq_st   = (const float*)d_in[8];
    const float* Wv_st   = (const float*)d_in[9];
    const float* W2k_ss  = (const float*)d_in[10];
    const float* W2q_ss  = (const float*)d_in[11];
    const float* W2v_ss  = (const float*)d_in[12];
    const float* W2k_se  = (const float*)d_in[13];
    const float* W2q_se  = (const float*)d_in[14];
    const float* W2v_se  = (const float*)d_in[15];
    const float* Wout_st = (const float*)d_in[16];
    float* out = (float*)d_out;

    float *kqvf,*stp,*att1,*kqv2,*a2,*stA,*stB;
    float *WkqvF,*WstP,*W2ss,*W2mid,*W2se;
    cudaGetSymbolAddress((void**)&kqvf, g_kqvf);
    cudaGetSymbolAddress((void**)&stp,  g_stp);
    cudaGetSymbolAddress((void**)&att1, g_att1);
    cudaGetSymbolAddress((void**)&kqv2, g_kqv2);
    cudaGetSymbolAddress((void**)&a2,   g_a2);
    cudaGetSymbolAddress((void**)&stA,  g_stA);
    cudaGetSymbolAddress((void**)&stB,  g_stB);
    cudaGetSymbolAddress((void**)&s_part, g_part);
    cudaGetSymbolAddress((void**)&WkqvF, g_WkqvF);
    cudaGetSymbolAddress((void**)&WstP,  g_WstP);
    cudaGetSymbolAddress((void**)&W2ss,  g_W2ss);
    cudaGetSymbolAddress((void**)&W2mid, g_W2mid);
    cudaGetSymbolAddress((void**)&W2se,  g_W2se);

    const int SM64  = (128*68 + 64*68 + 64*68 + 128*68) * 4;    // 104448
    const int SM128 = (128*132 + 64*132 + 128*68 + 128*68) * 4; // 171008
    cudaFuncSetAttribute(flash_k<64,false>,  cudaFuncAttributeMaxDynamicSharedMemorySize, SM64);
    cudaFuncSetAttribute(flash_k<128,true>,  cudaFuncAttributeMaxDynamicSharedMemorySize, SM128);

    // startup ordered so ncu (-s 5 -c 1) captures the full-projection GEMM
    bcast_state<<<(B_*SL_*D_ + 255)/256, 256>>>(stA, state);
    pack3<<<(H_*D_*192 + 255)/256, 256>>>(WkqvF, Wk, Wq, Wv, H_*D_, 64);
    pack3<<<(H_*D_*192 + 255)/256, 256>>>(WstP, Wk_st, Wq_st, Wv_st, H_*D_, 64);
    pack3<<<(H_*64*384 + 255)/256, 256>>>(W2ss,  W2k_ss, W2q_ss, W2v_ss, H_*64, 128);
    pack3<<<(H_*64*384 + 255)/256, 256>>>(W2mid, W2k,    W2k,    W2k,    H_*64, 128);

    // [launch 5] full-sequence K|Q|V projection
    G(false, x, WkqvF, kqvf, S_, 192, D_, D_, 192, 192,
      (long long)S_*D_, 0, 0, (long long)D_*192,
      (long long)H_*S_*192, (long long)S_*192, H_, B_*H_);

    pack3<<<(H_*64*384 + 255)/256, 256>>>(W2se,  W2k_se, W2q_se, W2v_se, H_*64, 128);

    BTab tab2; // level-2 projections: rows 0-127 ss, 128-639 mid, 640-767 se
    tab2.p[0] = W2ss; tab2.p[1] = W2mid; tab2.p[2] = W2mid;
    tab2.p[3] = W2mid; tab2.p[4] = W2mid; tab2.p[5] = W2se;
    tab2.p[6] = W2mid; tab2.p[7] = W2mid;

    BTab tabOS; // merged out/state: rows 0-511 Wout, 512-639 Wout_st
    tabOS.p[0] = Wout; tabOS.p[1] = Wout; tabOS.p[2] = Wout; tabOS.p[3] = Wout;
    tabOS.p[4] = Wout_st; tabOS.p[5] = Wout_st; tabOS.p[6] = Wout_st; tabOS.p[7] = Wout_st;

    for (int seg = 0; seg < NSEG_; seg++) {
        float* stc = (seg & 1) ? stB : stA;
        float* stn = (seg & 1) ? stA : stB;

        // state K|Q|V projection -> stp (split-K x2)
        G(false, stc, WstP, stp, SL_, 192, D_, D_, 192, 192,
          (long long)SL_*D_, 0, 0, (long long)D_*192,
          (long long)H_*SL_*192, (long long)SL_*192, H_, B_*H_, 2);

        // attention 1: region-mapped flash over [stp ; kqvf+segoff ; stp]
        flash_k<64,false><<<dim3(L_/128, B_*H_), 256, SM64>>>(
            stp, kqvf + (long long)seg*SEG_*192, 192,
            (long long)SL_*192, (long long)S_*192, 64, 0, 128, att1);

        // level-2 projections: single launch, per-row-block weights
        G(false, att1, nullptr, kqv2, L_, 384, DV_, DV_, 384, 384,
          (long long)H_*L_*DV_, (long long)L_*DV_, 0, (long long)64*384,
          (long long)H_*L_*384, (long long)L_*384, H_, B_*H_, 1, 1, tab2);

        // attention 2: skips rows [0,SL), writes unified a2 directly
        flash_k<128,true><<<dim3(L_/128 - 1, B_*H_), 256, SM128>>>(
            kqv2, nullptr, 384, (long long)L_*384, 0, 128, 0, 256, a2);

        // merged out-segment + next-state GEMM (split-K x2, custom reduce)
        G(false, a2, nullptr, nullptr, 640, D_, 2048, 2048, D_, D_,
          (long long)640*2048, 0, 0, 0, 0, 0, 1, B_, 2, 1, tabOS, 1);
        long long chunkOS = (long long)B_ * 640 * D_;
        reduceOS<<<(unsigned)((chunkOS + 255) / 256), 256>>>(
            out + (size_t)seg*SEG_*D_, stn, s_part, 2, chunkOS);
    }

    int st_elems = B_ * SL_ * D_;
    if (out_size >= B_*S_*D_ + st_elems) {
        copy_f<<<(st_elems + 255)/256, 256>>>(out + (size_t)B_*S_*D_, stA, st_elems);
    }
}

// round 7
// speedup vs baseline: 1.0949x; 1.0949x over previous
#include <cuda_runtime.h>
#include <cstdint>

#define B_ 2
#define S_ 2048
#define D_ 1024
#define H_ 16
#define DK_ 64
#define DV_ 64
#define SEG_ 512
#define SL_ 128
#define L_ 768
#define NSEG_ 4

// ---------------- scratch (device globals: allocation-free) ----------------
__device__ float g_kqvf[(size_t)B_*H_*S_*192];     // full-seq K|Q|V interleaved
__device__ float g_stp [(size_t)B_*H_*SL_*192];    // state K|Q|V projection
__device__ float g_att1[(size_t)B_*H_*L_*64];
__device__ float g_kqv2[(size_t)B_*H_*L_*384];     // k2|q2|v2 interleaved
__device__ float g_a2r [(size_t)B_*NSEG_*SEG_*2048]; // gathered a2, all segments
__device__ float g_a2e [(size_t)B_*SL_*2048];      // gathered a2e, current segment
__device__ float g_stA[(size_t)B_*SL_*D_];
__device__ float g_stB[(size_t)B_*SL_*D_];
__device__ float g_part[(size_t)4*1024*1024];
__device__ float g_WkqvF[(size_t)H_*D_*192];
__device__ float g_WstP [(size_t)H_*D_*192];
__device__ float g_W2ss [(size_t)H_*64*384];
__device__ float g_W2mid[(size_t)H_*64*384];
__device__ float g_W2se [(size_t)H_*64*384];

struct BTab { const float* p[8]; };

// ---------------- tf32 helpers ----------------
__device__ __forceinline__ uint32_t f2tf(float f) {
    uint32_t u;
    asm("cvt.rna.tf32.f32 %0, %1;" : "=r"(u) : "f"(f));
    return u;
}
__device__ __forceinline__ void mma8(float* c, const uint32_t* a, const uint32_t* b) {
    asm volatile(
        "mma.sync.aligned.m16n8k8.row.col.f32.tf32.tf32.f32 "
        "{%0,%1,%2,%3}, {%4,%5,%6,%7}, {%8,%9}, {%0,%1,%2,%3};\n"
        : "+f"(c[0]), "+f"(c[1]), "+f"(c[2]), "+f"(c[3])
        : "r"(a[0]), "r"(a[1]), "r"(a[2]), "r"(a[3]), "r"(b[0]), "r"(b[1]));
}
__device__ __forceinline__ int kperm(int k) {
    int j = k & 7;
    return (k & ~7) + ((j < 4) ? (j << 1) : ((j << 1) - 7));
}

// ---------------- batched strided tf32 tensor-core GEMM ----------------
template<int BM, int BN, int WM, int WN, bool TB>
__global__ void __launch_bounds__(256) gemm_t(
    const float* __restrict__ A, const float* __restrict__ Bm0, float* __restrict__ C,
    int M, int N, int K, int lda, int ldb, int ldc,
    long long aSB, long long aSH, long long bSB, long long bSH,
    long long cSB, long long cSH, int Hd, int Zr,
    int sk, int Kc, long long pcs, int useTab, BTab tab)
{
    constexpr int BK = 16;
    constexpr int KS = BK / 8;
    constexpr int MF = WM / 16;
    constexpr int NF = WN / 8;
    constexpr int WCOL = BN / WN;
    constexpr int NA4 = BM * BK / 1024;
    constexpr int NB4 = BN * BK / 1024;
    constexpr int KQ = BK / 4;

    int z = blockIdx.z;
    int ks = 0, zz = z;
    if (sk > 1) { ks = z / Zr; zz = z - ks * Zr; }
    int b = zz / Hd, h = zz - b * Hd;
    const float* Bm = useTab ? tab.p[blockIdx.y] : Bm0;
    A  += (long long)b * aSB + (long long)h * aSH;
    Bm += (long long)b * bSB + (long long)h * bSH;
    C  += (long long)ks * pcs + (long long)b * cSB + (long long)h * cSH;

    int row0 = blockIdx.y * BM;
    int col0 = blockIdx.x * BN;

    int kBeg = ks * Kc;
    int nk = Kc / BK;

    __shared__ uint32_t As[2][BM][BK + 4];
    __shared__ uint32_t Bs[2][BN][BK + 4];

    int tid = threadIdx.x;
    int w   = tid >> 5;
    int lane = tid & 31;
    int g = lane >> 2, q = lane & 3;
    int warpM = w / WCOL, warpN = w % WCOL;
    int wr = warpM * WM;
    int wc = warpN * WN;

    float4 ag[NA4], bg[NB4];

    {
        int kb = kBeg;
        #pragma unroll
        for (int i = 0; i < NA4; i++) {
            int f = tid + i * 256; int r = f / KQ; int c4 = (f % KQ) << 2;
            float4 v = *(const float4*)(A + (long long)(row0 + r) * lda + kb + c4);
            As[0][r][kperm(c4+0)] = f2tf(v.x);
            As[0][r][kperm(c4+1)] = f2tf(v.y);
            As[0][r][kperm(c4+2)] = f2tf(v.z);
            As[0][r][kperm(c4+3)] = f2tf(v.w);
        }
        if (!TB) {
            #pragma unroll
            for (int i = 0; i < NB4; i++) {
                int f = tid + i * 256; int kr = f / (BN/4); int n4 = (f % (BN/4)) << 2;
                float4 v = *(const float4*)(Bm + (long long)(kb + kr) * ldb + col0 + n4);
                int kp = kperm(kr);
                Bs[0][n4+0][kp] = f2tf(v.x);
                Bs[0][n4+1][kp] = f2tf(v.y);
                Bs[0][n4+2][kp] = f2tf(v.z);
                Bs[0][n4+3][kp] = f2tf(v.w);
            }
        } else {
            #pragma unroll
            for (int i = 0; i < NB4; i++) {
                int f = tid + i * 256; int r = f / KQ; int c4 = (f % KQ) << 2;
                float4 v = *(const float4*)(Bm + (long long)(col0 + r) * ldb + kb + c4);
                Bs[0][r][kperm(c4+0)] = f2tf(v.x);
                Bs[0][r][kperm(c4+1)] = f2tf(v.y);
                Bs[0][r][kperm(c4+2)] = f2tf(v.z);
                Bs[0][r][kperm(c4+3)] = f2tf(v.w);
            }
        }
    }
    __syncthreads();

    float acc[MF][NF][4];
    #pragma unroll
    for (int i = 0; i < MF; i++)
        #pragma unroll
        for (int j = 0; j < NF; j++)
            #pragma unroll
            for (int e = 0; e < 4; e++) acc[i][j][e] = 0.f;

    int cur = 0;
    for (int t = 0; t < nk; t++) {
        if (t + 1 < nk) {
            int kb = kBeg + (t + 1) * BK;
            #pragma unroll
            for (int i = 0; i < NA4; i++) {
                int f = tid + i * 256; int r = f / KQ; int c4 = (f % KQ) << 2;
                ag[i] = *(const float4*)(A + (long long)(row0 + r) * lda + kb + c4);
            }
            if (!TB) {
                #pragma unroll
                for (int i = 0; i < NB4; i++) {
                    int f = tid + i * 256; int kr = f / (BN/4); int n4 = (f % (BN/4)) << 2;
                    bg[i] = *(const float4*)(Bm + (long long)(kb + kr) * ldb + col0 + n4);
                }
            } else {
                #pragma unroll
                for (int i = 0; i < NB4; i++) {
                    int f = tid + i * 256; int r = f / KQ; int c4 = (f % KQ) << 2;
                    bg[i] = *(const float4*)(Bm + (long long)(col0 + r) * ldb + kb + c4);
                }
            }
        }
        #pragma unroll
        for (int s = 0; s < KS; s++) {
            uint32_t af[MF][4], bf[NF][2];
            #pragma unroll
            for (int i = 0; i < MF; i++) {
                uint2 lo = *(const uint2*)&As[cur][wr + 16*i + g    ][8*s + 2*q];
                uint2 hi = *(const uint2*)&As[cur][wr + 16*i + g + 8][8*s + 2*q];
                af[i][0] = lo.x; af[i][1] = hi.x; af[i][2] = lo.y; af[i][3] = hi.y;
            }
            #pragma unroll
            for (int j = 0; j < NF; j++) {
                uint2 bb = *(const uint2*)&Bs[cur][wc + 8*j + g][8*s + 2*q];
                bf[j][0] = bb.x; bf[j][1] = bb.y;
            }
            #pragma unroll
            for (int i = 0; i < MF; i++)
                #pragma unroll
                for (int j = 0; j < NF; j++)
                    mma8(acc[i][j], af[i], bf[j]);
        }
        if (t + 1 < nk) {
            int nxt = cur ^ 1;
            #pragma unroll
            for (int i = 0; i < NA4; i++) {
                int f = tid + i * 256; int r = f / KQ; int c4 = (f % KQ) << 2;
                As[nxt][r][kperm(c4+0)] = f2tf(ag[i].x);
                As[nxt][r][kperm(c4+1)] = f2tf(ag[i].y);
                As[nxt][r][kperm(c4+2)] = f2tf(ag[i].z);
                As[nxt][r][kperm(c4+3)] = f2tf(ag[i].w);
            }
            if (!TB) {
                #pragma unroll
                for (int i = 0; i < NB4; i++) {
                    int f = tid + i * 256; int kr = f / (BN/4); int n4 = (f % (BN/4)) << 2;
                    int kp = kperm(kr);
                    Bs[nxt][n4+0][kp] = f2tf(bg[i].x);
                    Bs[nxt][n4+1][kp] = f2tf(bg[i].y);
                    Bs[nxt][n4+2][kp] = f2tf(bg[i].z);
                    Bs[nxt][n4+3][kp] = f2tf(bg[i].w);
                }
            } else {
                #pragma unroll
                for (int i = 0; i < NB4; i++) {
                    int f = tid + i * 256; int r = f / KQ; int c4 = (f % KQ) << 2;
                    Bs[nxt][r][kperm(c4+0)] = f2tf(bg[i].x);
                    Bs[nxt][r][kperm(c4+1)] = f2tf(bg[i].y);
                    Bs[nxt][r][kperm(c4+2)] = f2tf(bg[i].z);
                    Bs[nxt][r][kperm(c4+3)] = f2tf(bg[i].w);
                }
            }
            __syncthreads();
            cur = nxt;
        }
    }

    #pragma unroll
    for (int i = 0; i < MF; i++) {
        #pragma unroll
        for (int j = 0; j < NF; j++) {
            int r0 = row0 + wr + 16*i + g;
            int c0 = col0 + wc + 8*j + 2*q;
            *(float2*)(C + (long long)r0 * ldc + c0) = make_float2(acc[i][j][0], acc[i][j][1]);
            *(float2*)(C + (long long)(r0 + 8) * ldc + c0) = make_float2(acc[i][j][2], acc[i][j][3]);
        }
    }
}

// ---------------- fused flash attention (tf32 mma, online softmax) ----------
// GATHER=0 (attn1): region-mapped inputs [state; segment; state]; dense out0.
// GATHER=1 (attn2): dense input b1; skip rows [0,SL);
//                   a2 rows -> out0 (+b*o0b), a2e rows -> out1.
template<int DH, bool GATHER>
__global__ void __launch_bounds__(256) flash_k(
    const float* __restrict__ b1, const float* __restrict__ b2, int ld,
    long long b1S, long long b2S, int qoff, int koff, int voff,
    float* __restrict__ out0, long long o0b, float* __restrict__ out1)
{
    constexpr int BR = 128, BC = 64;
    constexpr int QW = DH + 4, KW = DH + 4, VW = BC + 4, SW = BC + 4;
    extern __shared__ uint32_t sm[];
    uint32_t* Qs = sm;
    uint32_t* Ks = Qs + BR * QW;
    uint32_t* Vs = Ks + BC * KW;
    uint32_t* Ss = Vs + DH * VW;

    int bh = blockIdx.y;
    int b = bh / H_, h = bh - b * H_;

    const float* stb  = b1 + (long long)bh * b1S;
    const float* segb = GATHER ? stb : (b2 + (long long)bh * b2S);

    int row0 = (GATHER ? (blockIdx.x + 1) : blockIdx.x) * BR;

    const float* Qb;
    if (GATHER) {
        Qb = stb + (long long)row0 * ld;
    } else {
        if (row0 < SL_)            Qb = stb;
        else if (row0 < SL_+SEG_)  Qb = segb + (long long)(row0 - SL_) * ld;
        else                       Qb = stb;
    }

    int tid = threadIdx.x, w = tid >> 5, lane = tid & 31;
    int g = lane >> 2, q = lane & 3;
    int wr = w * 16;

    constexpr int NQ4 = BR * DH / 1024;
    #pragma unroll
    for (int i = 0; i < NQ4; i++) {
        int f = tid + i * 256; int r = f / (DH/4); int c4 = (f % (DH/4)) << 2;
        float4 v = *(const float4*)(Qb + (long long)r * ld + qoff + c4);
        Qs[r*QW + kperm(c4+0)] = f2tf(v.x);
        Qs[r*QW + kperm(c4+1)] = f2tf(v.y);
        Qs[r*QW + kperm(c4+2)] = f2tf(v.z);
        Qs[r*QW + kperm(c4+3)] = f2tf(v.w);
    }

    float Ofr[DH/8][4];
    #pragma unroll
    for (int j = 0; j < DH/8; j++)
        #pragma unroll
        for (int e = 0; e < 4; e++) Ofr[j][e] = 0.f;
    float m_a = -1e30f, m_b = -1e30f, l_a = 0.f, l_b = 0.f;
    int row_a = row0 + wr + g, row_b = row_a + 8;

    int nb = row0 / BC + 2;
    constexpr int NK4 = BC * DH / 1024;

    for (int cb = 0; cb < nb; cb++) {
        int c0 = cb * BC;
        const float* Kb;
        if (GATHER) {
            Kb = stb + (long long)c0 * ld;
        } else {
            if (c0 < SL_)            Kb = stb + (long long)c0 * ld;
            else if (c0 < SL_+SEG_)  Kb = segb + (long long)(c0 - SL_) * ld;
            else                     Kb = stb + (long long)(c0 - SL_ - SEG_) * ld;
        }
        __syncthreads();
        #pragma unroll
        for (int i = 0; i < NK4; i++) {
            int f = tid + i * 256; int r = f / (DH/4); int c4 = (f % (DH/4)) << 2;
            float4 v = *(const float4*)(Kb + (long long)r * ld + koff + c4);
            Ks[r*KW + kperm(c4+0)] = f2tf(v.x);
            Ks[r*KW + kperm(c4+1)] = f2tf(v.y);
            Ks[r*KW + kperm(c4+2)] = f2tf(v.z);
            Ks[r*KW + kperm(c4+3)] = f2tf(v.w);
        }
        #pragma unroll
        for (int i = 0; i < NK4; i++) {
            int f = tid + i * 256; int c = f / (DH/4); int d4 = (f % (DH/4)) << 2;
            float4 v = *(const float4*)(Kb + (long long)c * ld + voff + d4);
            int kp = kperm(c);
            Vs[(d4+0)*VW + kp] = f2tf(v.x);
            Vs[(d4+1)*VW + kp] = f2tf(v.y);
            Vs[(d4+2)*VW + kp] = f2tf(v.z);
            Vs[(d4+3)*VW + kp] = f2tf(v.w);
        }
        __syncthreads();

        float sfr[BC/8][4];
        #pragma unroll
        for (int j = 0; j < BC/8; j++)
            #pragma unroll
            for (int e = 0; e < 4; e++) sfr[j][e] = 0.f;
        #pragma unroll
        for (int s = 0; s < DH/8; s++) {
            uint32_t af[4];
            uint2 lo = *(const uint2*)&Qs[(wr+g  )*QW + 8*s + 2*q];
            uint2 hi = *(const uint2*)&Qs[(wr+g+8)*QW + 8*s + 2*q];
            af[0] = lo.x; af[1] = hi.x; af[2] = lo.y; af[3] = hi.y;
            #pragma unroll
            for (int j = 0; j < BC/8; j++) {
                uint2 bb = *(const uint2*)&Ks[(8*j+g)*KW + 8*s + 2*q];
                uint32_t bf[2] = {bb.x, bb.y};
                mma8(sfr[j], af, bf);
            }
        }

        bool needm = (c0 + BC - 1 > row0 + wr);
        float mb_a = -1e30f, mb_b = -1e30f;
        #pragma unroll
        for (int j = 0; j < BC/8; j++) {
            int col = c0 + 8*j + 2*q;
            float s0 = sfr[j][0]*0.125f, s1 = sfr[j][1]*0.125f;
            float s2 = sfr[j][2]*0.125f, s3 = sfr[j][3]*0.125f;
            if (needm) {
                if (col     > row_a) s0 = -1e30f;
                if (col + 1 > row_a) s1 = -1e30f;
                if (col     > row_b) s2 = -1e30f;
                if (col + 1 > row_b) s3 = -1e30f;
            }
            sfr[j][0]=s0; sfr[j][1]=s1; sfr[j][2]=s2; sfr[j][3]=s3;
            mb_a = fmaxf(mb_a, fmaxf(s0, s1));
            mb_b = fmaxf(mb_b, fmaxf(s2, s3));
        }
        mb_a = fmaxf(mb_a, __shfl_xor_sync(0xffffffffu, mb_a, 1));
        mb_a = fmaxf(mb_a, __shfl_xor_sync(0xffffffffu, mb_a, 2));
        mb_b = fmaxf(mb_b, __shfl_xor_sync(0xffffffffu, mb_b, 1));
        mb_b = fmaxf(mb_b, __shfl_xor_sync(0xffffffffu, mb_b, 2));
        float mn_a = fmaxf(m_a, mb_a), mn_b = fmaxf(m_b, mb_b);
        float ra = __expf(m_a - mn_a), rb = __expf(m_b - mn_b);
        float sa = 0.f, sb = 0.f;
        #pragma unroll
        for (int j = 0; j < BC/8; j++) {
            float p0 = __expf(sfr[j][0] - mn_a), p1 = __expf(sfr[j][1] - mn_a);
            float p2 = __expf(sfr[j][2] - mn_b), p3 = __expf(sfr[j][3] - mn_b);
            sa += p0 + p1; sb += p2 + p3;
            int cc = 8*j + 2*q;
            Ss[(wr+g  )*SW + kperm(cc  )] = f2tf(p0);
            Ss[(wr+g  )*SW + kperm(cc+1)] = f2tf(p1);
            Ss[(wr+g+8)*SW + kperm(cc  )] = f2tf(p2);
            Ss[(wr+g+8)*SW + kperm(cc+1)] = f2tf(p3);
        }
        sa += __shfl_xor_sync(0xffffffffu, sa, 1);
        sa += __shfl_xor_sync(0xffffffffu, sa, 2);
        sb += __shfl_xor_sync(0xffffffffu, sb, 1);
        sb += __shfl_xor_sync(0xffffffffu, sb, 2);
        l_a = l_a * ra + sa; l_b = l_b * rb + sb;
        m_a = mn_a; m_b = mn_b;
        #pragma unroll
        for (int j2 = 0; j2 < DH/8; j2++) {
            Ofr[j2][0] *= ra; Ofr[j2][1] *= ra;
            Ofr[j2][2] *= rb; Ofr[j2][3] *= rb;
        }
        __syncwarp();

        #pragma unroll
        for (int s = 0; s < BC/8; s++) {
            uint32_t af[4];
            uint2 lo = *(const uint2*)&Ss[(wr+g  )*SW + 8*s + 2*q];
            uint2 hi = *(const uint2*)&Ss[(wr+g+8)*SW + 8*s + 2*q];
            af[0] = lo.x; af[1] = hi.x; af[2] = lo.y; af[3] = hi.y;
            #pragma unroll
            for (int j2 = 0; j2 < DH/8; j2++) {
                uint2 bb = *(const uint2*)&Vs[(8*j2+g)*VW + 8*s + 2*q];
                uint32_t bf[2] = {bb.x, bb.y};
                mma8(Ofr[j2], af, bf);
            }
        }
    }

    float ia = 1.f / l_a, ib = 1.f / l_b;
    if (!GATHER) {
        float* oa = out0 + (long long)bh * L_ * DH + (long long)row_a * DH;
        float* ob = out0 + (long long)bh * L_ * DH + (long long)row_b * DH;
        #pragma unroll
        for (int j2 = 0; j2 < DH/8; j2++) {
            int col = 8*j2 + 2*q;
            *(float2*)(oa + col) = make_float2(Ofr[j2][0]*ia, Ofr[j2][1]*ia);
            *(float2*)(ob + col) = make_float2(Ofr[j2][2]*ib, Ofr[j2][3]*ib);
        }
    } else {
        #pragma unroll
        for (int rr = 0; rr < 2; rr++) {
            int s_abs = (rr == 0) ? row_a : row_b;
            float inv = (rr == 0) ? ia : ib;
            float* dst;
            if (s_abs < SL_ + SEG_) {
                int s = s_abs - SL_;
                dst = out0 + (long long)b * o0b
                    + (long long)((h << 5) + (s >> 4)) * 2048 + ((s & 15) << 7);
            } else {
                int s = s_abs - (SL_ + SEG_);
                dst = out1 + ((long long)b * SL_ + (h << 3) + (s >> 4)) * 2048
                    + ((s & 15) << 7);
            }
            #pragma unroll
            for (int j2 = 0; j2 < DH/8; j2++) {
                int col = 8*j2 + 2*q;
                float v0 = Ofr[j2][rr ? 2 : 0] * inv;
                float v1 = Ofr[j2][rr ? 3 : 1] * inv;
                *(float2*)(dst + col) = make_float2(v0, v1);
            }
        }
    }
}

// generic split-K reduce
__global__ void reduceK(float* __restrict__ C, const float* __restrict__ part,
    int sk, long long chunk, int M, int N, int ldc,
    long long cSB, long long cSH, int Hd)
{
    long long idx = (long long)blockIdx.x * blockDim.x + threadIdx.x;
    if (idx >= chunk) return;
    int n = (int)(idx % N);
    long long t = idx / N;
    int m = (int)(t % M);
    int zz = (int)(t / M);
    int b = zz / Hd, h = zz - b * Hd;
    float s = 0.f;
    for (int i = 0; i < sk; i++) s += part[(long long)i * chunk + idx];
    C[(long long)b * cSB + (long long)h * cSH + (long long)m * ldc + n] = s;
}

__global__ void pack3(float* __restrict__ dst, const float* __restrict__ s0,
                      const float* __restrict__ s1, const float* __restrict__ s2,
                      int n, int w)
{
    int idx = blockIdx.x * blockDim.x + threadIdx.x;
    int tot = n * 3 * w;
    if (idx >= tot) return;
    int c = idx % w; int o = (idx / w) % 3; int i = idx / (3 * w);
    const float* s = (o == 0) ? s0 : ((o == 1) ? s1 : s2);
    dst[idx] = s[(size_t)i * w + c];
}

__global__ void bcast_state(float* __restrict__ st, const float* __restrict__ state)
{
    int idx = blockIdx.x * blockDim.x + threadIdx.x;
    const int total = B_ * SL_ * D_;
    if (idx >= total) return;
    st[idx] = state[idx % (SL_ * D_)];
}

__global__ void copy_f(float* __restrict__ dst, const float* __restrict__ src, int n)
{
    int idx = blockIdx.x * blockDim.x + threadIdx.x;
    if (idx < n) dst[idx] = src[idx];
}

// ---------------- host ----------------
static float* s_part = nullptr;

static void G(bool tb, const float* A, const float* Bm, float* C,
              int M, int N, int K, int lda, int ldb, int ldc,
              long long aSB, long long aSH, long long bSB, long long bSH,
              long long cSB, long long cSH, int Hd, int Z, int sk = 1,
              int useTab = 0, BTab tab = {})
{
    int Kc = K / sk;
    long long pcs = 0;
    float* Cout = C;
    long long csb = cSB, csh = cSH;
    int ldc2 = ldc;
    if (sk > 1) {
        pcs = (long long)Z * M * N;
        Cout = s_part; ldc2 = N;
        csh = (long long)M * N;
        csb = (long long)Hd * M * N;
    }
    dim3 blk(256);
    if (N % 128 == 0) {
        dim3 grid(N / 128, (M + 127) / 128, Z * sk);
        if (tb) gemm_t<128,128,64,32,true ><<<grid, blk>>>(A, Bm, Cout, M, N, K, lda, ldb, ldc2,
            aSB, aSH, bSB, bSH, csb, csh, Hd, Z, sk, Kc, pcs, useTab, tab);
        else    gemm_t<128,128,64,32,false><<<grid, blk>>>(A, Bm, Cout, M, N, K, lda, ldb, ldc2,
            aSB, aSH, bSB, bSH, csb, csh, Hd, Z, sk, Kc, pcs, useTab, tab);
    } else {
        dim3 grid(N / 64, (M + 127) / 128, Z * sk);
        if (tb) gemm_t<128,64,32,32,true ><<<grid, blk>>>(A, Bm, Cout, M, N, K, lda, ldb, ldc2,
            aSB, aSH, bSB, bSH, csb, csh, Hd, Z, sk, Kc, pcs, useTab, tab);
        else    gemm_t<128,64,32,32,false><<<grid, blk>>>(A, Bm, Cout, M, N, K, lda, ldb, ldc2,
            aSB, aSH, bSB, bSH, csb, csh, Hd, Z, sk, Kc, pcs, useTab, tab);
    }
    if (sk > 1) {
        long long chunk = (long long)Z * M * N;
        reduceK<<<(unsigned)((chunk + 255) / 256), 256>>>(C, s_part, sk, chunk,
            M, N, ldc, cSB, cSH, Hd);
    }
}

extern "C" void kernel_launch(void* const* d_in, const int* in_sizes, int n_in,
                              void* d_out, int out_size)
{
    const float* x       = (const float*)d_in[0];
    const float* state   = (const float*)d_in[1];
    const float* Wk      = (const float*)d_in[2];
    const float* Wq      = (const float*)d_in[3];
    const float* Wv      = (const float*)d_in[4];
    const float* W2k     = (const float*)d_in[5];
    const float* Wout    = (const float*)d_in[6];
    const float* Wk_st   = (const float*)d_in[7];
    const float* Wq_st   = (const float*)d_in[8];
    const float* Wv_st   = (const float*)d_in[9];
    const float* W2k_ss  = (const float*)d_in[10];
    const float* W2q_ss  = (const float*)d_in[11];
    const float* W2v_ss  = (const float*)d_in[12];
    const float* W2k_se  = (const float*)d_in[13];
    const float* W2q_se  = (const float*)d_in[14];
    const float* W2v_se  = (const float*)d_in[15];
    const float* Wout_st = (const float*)d_in[16];
    float* out = (float*)d_out;

    float *kqvf,*stp,*att1,*kqv2,*a2r,*a2e,*stA,*stB;
    float *WkqvF,*WstP,*W2ss,*W2mid,*W2se;
    cudaGetSymbolAddress((void**)&kqvf, g_kqvf);
    cudaGetSymbolAddress((void**)&stp,  g_stp);
    cudaGetSymbolAddress((void**)&att1, g_att1);
    cudaGetSymbolAddress((void**)&kqv2, g_kqv2);
    cudaGetSymbolAddress((void**)&a2r,  g_a2r);
    cudaGetSymbolAddress((void**)&a2e,  g_a2e);
    cudaGetSymbolAddress((void**)&stA,  g_stA);
    cudaGetSymbolAddress((void**)&stB,  g_stB);
    cudaGetSymbolAddress((void**)&s_part, g_part);
    cudaGetSymbolAddress((void**)&WkqvF, g_WkqvF);
    cudaGetSymbolAddress((void**)&WstP,  g_WstP);
    cudaGetSymbolAddress((void**)&W2ss,  g_W2ss);
    cudaGetSymbolAddress((void**)&W2mid, g_W2mid);
    cudaGetSymbolAddress((void**)&W2se,  g_W2se);

    const int SM64  = (128*68 + 64*68 + 64*68 + 128*68) * 4;    // 104448
    const int SM128 = (128*132 + 64*132 + 128*68 + 128*68) * 4; // 171008
    cudaFuncSetAttribute(flash_k<64,false>,  cudaFuncAttributeMaxDynamicSharedMemorySize, SM64);
    cudaFuncSetAttribute(flash_k<128,true>,  cudaFuncAttributeMaxDynamicSharedMemorySize, SM128);

    bcast_state<<<(B_*SL_*D_ + 255)/256, 256>>>(stA, state);
    pack3<<<(H_*D_*192 + 255)/256, 256>>>(WkqvF, Wk, Wq, Wv, H_*D_, 64);
    pack3<<<(H_*D_*192 + 255)/256, 256>>>(WstP, Wk_st, Wq_st, Wv_st, H_*D_, 64);
    pack3<<<(H_*64*384 + 255)/256, 256>>>(W2ss,  W2k_ss, W2q_ss, W2v_ss, H_*64, 128);
    pack3<<<(H_*64*384 + 255)/256, 256>>>(W2mid, W2k,    W2k,    W2k,    H_*64, 128);
    pack3<<<(H_*64*384 + 255)/256, 256>>>(W2se,  W2k_se, W2q_se, W2v_se, H_*64, 128);

    // full-sequence K|Q|V projection
    G(false, x, WkqvF, kqvf, S_, 192, D_, D_, 192, 192,
      (long long)S_*D_, 0, 0, (long long)D_*192,
      (long long)H_*S_*192, (long long)S_*192, H_, B_*H_);

    BTab tab2; // level-2 projections: rows 0-127 ss, 128-639 mid, 640-767 se
    tab2.p[0] = W2ss; tab2.p[1] = W2mid; tab2.p[2] = W2mid;
    tab2.p[3] = W2mid; tab2.p[4] = W2mid; tab2.p[5] = W2se;
    tab2.p[6] = W2mid; tab2.p[7] = W2mid;

    for (int seg = 0; seg < NSEG_; seg++) {
        float* stc = (seg & 1) ? stB : stA;
        float* stn = (seg & 1) ? stA : stB;

        // state K|Q|V projection -> stp (split-K x2)
        G(false, stc, WstP, stp, SL_, 192, D_, D_, 192, 192,
          (long long)SL_*D_, 0, 0, (long long)D_*192,
          (long long)H_*SL_*192, (long long)SL_*192, H_, B_*H_, 2);

        // attention 1: region-mapped flash over [stp ; kqvf+segoff ; stp]
        flash_k<64,false><<<dim3(L_/128, B_*H_), 256, SM64>>>(
            stp, kqvf + (long long)seg*SEG_*192, 192,
            (long long)SL_*192, (long long)S_*192, 64, 0, 128, att1, 0, nullptr);

        // level-2 projections: single launch, per-row-block weights
        G(false, att1, nullptr, kqv2, L_, 384, DV_, DV_, 384, 384,
          (long long)H_*L_*DV_, (long long)L_*DV_, 0, (long long)64*384,
          (long long)H_*L_*384, (long long)L_*384, H_, B_*H_, 1, 1, tab2);

        // attention 2: skips rows [0,SL); a2 -> persistent per-seg buffer, a2e -> a2e
        flash_k<128,true><<<dim3(L_/128 - 1, B_*H_), 256, SM128>>>(
            kqv2, nullptr, 384, (long long)L_*384, 0, 128, 0, 256,
            a2r + (long long)seg*SEG_*2048, (long long)NSEG_*SEG_*2048, a2e);

        // next state only (split-K x8) — the one thing the next segment waits on
        G(false, a2e, Wout_st, stn, SL_, D_, 2048, 2048, D_, D_,
          (long long)SL_*2048, 0, 0, 0, (long long)SL_*D_, 0, 1, B_, 8);
    }

    // deferred: all out-segment projections in ONE batched GEMM (Z = B*NSEG)
    G(false, a2r, Wout, out, SEG_, D_, 2048, 2048, D_, D_,
      (long long)NSEG_*SEG_*2048, (long long)SEG_*2048, 0, 0,
      (long long)S_*D_, (long long)SEG_*D_, NSEG_, B_*NSEG_);

    int st_elems = B_ * SL_ * D_;
    if (out_size >= B_*S_*D_ + st_elems) {
        copy_f<<<(st_elems + 255)/256, 256>>>(out + (size_t)B_*S_*D_, stA, st_elems);
    }
}